// round 2
// baseline (speedup 1.0000x reference)
#include <cuda_runtime.h>
#include <cuda_bf16.h>

#define GAMMAK (1.0f/256.0f)
#define NROWS 8191            // valid query/key rows
#define D 128

// ---------------- scratch (device globals: no allocation allowed) ----------
__device__ float g_yt[8192 * 128];   // yt padded to 8192 rows
__device__ float g_kn[8192];         // ||yt_j||^2, padded row -> 1e30 (weight 0)
__device__ float g_qn[8192];         // ||X_i||^2

// ---------------- kernel 1: yt = y @ R^T + t  (64 rows / CTA) --------------
// smem: yT [128][68] transposed  (34816 B)  +  RT [128][132] transposed (67584 B)
__global__ __launch_bounds__(256) void yt_kernel(const float* __restrict__ y,
                                                 const float* __restrict__ R,
                                                 const float* __restrict__ t)
{
    extern __shared__ char smem[];
    float* yT = (float*)smem;                 // [k][row] stride 68
    float* RT = (float*)(smem + 34816);       // [k][c]   stride 132
    const int tid = threadIdx.x;
    const int r0  = blockIdx.x * 64;

    // load y tile transposed (coalesced gmem, 4-way-conflict STS at worst)
    #pragma unroll
    for (int s = 0; s < 32; s++) {
        int e = tid + s * 256;                // 0..8191
        int row = e >> 7, k = e & 127;
        int gr = r0 + row;
        float v = (gr < NROWS) ? y[gr * 128 + k] : 0.0f;
        yT[k * 68 + row] = v;
    }
    // load R transposed: RT[k][c] = R[c][k]
    #pragma unroll
    for (int s = 0; s < 64; s++) {
        int e = tid + s * 256;                // 0..16383
        int c = e >> 7, k = e & 127;
        RT[k * 132 + c] = R[e];
    }
    __syncthreads();

    const int tr = tid >> 4, tc = tid & 15;   // 16x16 threads, 4 rows x 8 cols each
    float acc[4][8];
    #pragma unroll
    for (int i = 0; i < 4; i++)
        #pragma unroll
        for (int j = 0; j < 8; j++) acc[i][j] = 0.0f;

    const float4* yT4 = (const float4*)yT;    // row stride 17 float4
    const float4* RT4 = (const float4*)RT;    // row stride 33 float4

    #pragma unroll 8
    for (int k = 0; k < 128; k++) {
        float4 a  = yT4[k * 17 + tr];
        float4 b0 = RT4[k * 33 + tc * 2];
        float4 b1 = RT4[k * 33 + tc * 2 + 1];
        float av[4] = {a.x, a.y, a.z, a.w};
        float bv[8] = {b0.x, b0.y, b0.z, b0.w, b1.x, b1.y, b1.z, b1.w};
        #pragma unroll
        for (int i = 0; i < 4; i++)
            #pragma unroll
            for (int j = 0; j < 8; j++) acc[i][j] += av[i] * bv[j];
    }

    float tv[8];
    #pragma unroll
    for (int j = 0; j < 8; j++) tv[j] = t[tc * 8 + j];

    float4* yt4 = (float4*)g_yt;
    #pragma unroll
    for (int i = 0; i < 4; i++) {
        int row = r0 + tr * 4 + i;
        float4 o0, o1;
        o0.x = acc[i][0] + tv[0];  o0.y = acc[i][1] + tv[1];
        o0.z = acc[i][2] + tv[2];  o0.w = acc[i][3] + tv[3];
        o1.x = acc[i][4] + tv[4];  o1.y = acc[i][5] + tv[5];
        o1.z = acc[i][6] + tv[6];  o1.w = acc[i][7] + tv[7];
        yt4[row * 32 + tc * 2]     = o0;
        yt4[row * 32 + tc * 2 + 1] = o1;
    }
}

// ---------------- kernel 2: row sum-of-squares for X (qn) and yt (kn) ------
__global__ __launch_bounds__(128) void norm_kernel(const float* __restrict__ X)
{
    const int row   = blockIdx.x;
    const int which = blockIdx.y;             // 0 -> qn(X), 1 -> kn(yt)
    const float* src = which ? g_yt : X;
    float v = src[row * 128 + threadIdx.x];
    float s = v * v;
    #pragma unroll
    for (int o = 16; o; o >>= 1) s += __shfl_down_sync(0xFFFFFFFFu, s, o);
    __shared__ float red[4];
    if ((threadIdx.x & 31) == 0) red[threadIdx.x >> 5] = s;
    __syncthreads();
    if (threadIdx.x == 0) {
        float tot = red[0] + red[1] + red[2] + red[3];
        if (which) g_kn[row] = (row < NROWS) ? tot : 1e30f;  // pad key -> weight 0
        else       g_qn[row] = tot;
    }
}

// ---------------- kernel 3: fused RBF attention ----------------------------
// BM=64 queries/CTA, BN=64 keys/tile, d=128. 256 threads (16x16).
// smem layout (bytes):
//   Qt  [128][68]  @ 0       (34816)
//   Kt  [128][68]  @ 34816   (34816)
//   Vs  [64][128]  @ 69632   (32768)
//   Pt  [64][68]   @ 102400  (17408)   -- P transposed: [key][query]
//   qn_s[64]       @ 119808
//   kn_s[64]       @ 120064
// total 120320 B
__global__ __launch_bounds__(256) void attn_kernel(const float* __restrict__ X,
                                                   float* __restrict__ out)
{
    extern __shared__ char smem[];
    float* Qt   = (float*)smem;
    float* Kt   = (float*)(smem + 34816);
    float* Vs   = (float*)(smem + 69632);
    float* Pt   = (float*)(smem + 102400);
    float* qn_s = (float*)(smem + 119808);
    float* kn_s = (float*)(smem + 120064);

    const int tid = threadIdx.x;
    const int tr  = tid >> 4, tc = tid & 15;
    const int r0  = blockIdx.x * 64;

    // Q tile (X rows r0..r0+63; row 8191 exists in X, output guarded later)
    #pragma unroll
    for (int s = 0; s < 32; s++) {
        int e = tid + s * 256;
        int row = e >> 7, k = e & 127;
        Qt[k * 68 + row] = X[(r0 + row) * 128 + k];
    }
    if (tid < 64) qn_s[tid] = g_qn[r0 + tid];
    __syncthreads();

    float acc[4][8];
    float den[4] = {0.f, 0.f, 0.f, 0.f};
    #pragma unroll
    for (int i = 0; i < 4; i++)
        #pragma unroll
        for (int j = 0; j < 8; j++) acc[i][j] = 0.0f;

    const float4* Qt4 = (const float4*)Qt;   // stride 17
    const float4* Kt4 = (const float4*)Kt;   // stride 17
    const float4* Vs4 = (const float4*)Vs;   // stride 32
    float4*       VsW = (float4*)Vs;
    const float4* Pt4 = (const float4*)Pt;   // stride 17
    float4*       PtW = (float4*)Pt;
    const float4* X4  = (const float4*)X;

    float qnv[4];
    #pragma unroll
    for (int i = 0; i < 4; i++) qnv[i] = qn_s[tr * 4 + i];

    for (int tile = 0; tile < 128; tile++) {
        const int j0 = tile * 64;

        // ---- stage K (transposed), V, kn ----
        #pragma unroll
        for (int s = 0; s < 32; s++) {
            int e = tid + s * 256;
            int row = e >> 7, k = e & 127;
            Kt[k * 68 + row] = g_yt[(j0 + row) * 128 + k];
        }
        #pragma unroll
        for (int s = 0; s < 8; s++) {
            int idx = tid + s * 256;          // float4 index 0..2047
            int row = idx >> 5, c4 = idx & 31;
            int jg = j0 + row;
            float4 v = (jg < NROWS) ? X4[(jg + 1) * 32 + c4]
                                    : make_float4(0.f, 0.f, 0.f, 0.f);
            VsW[row * 32 + c4] = v;
        }
        if (tid < 64) kn_s[tid] = g_kn[j0 + tid];
        __syncthreads();

        // ---- S = Q @ K^T (4x4 per thread) ----
        float sa[4][4];
        #pragma unroll
        for (int i = 0; i < 4; i++)
            #pragma unroll
            for (int j = 0; j < 4; j++) sa[i][j] = 0.0f;

        #pragma unroll 8
        for (int k = 0; k < 128; k++) {
            float4 a = Qt4[k * 17 + tr];
            float4 b = Kt4[k * 17 + tc];
            float av[4] = {a.x, a.y, a.z, a.w};
            float bv[4] = {b.x, b.y, b.z, b.w};
            #pragma unroll
            for (int i = 0; i < 4; i++)
                #pragma unroll
                for (int j = 0; j < 4; j++) sa[i][j] += av[i] * bv[j];
        }

        // ---- P = exp(-gamma * clip(qn + kn - 2S, 0)) ; store transposed ----
        #pragma unroll
        for (int j = 0; j < 4; j++) {
            float knc = kn_s[tc * 4 + j];
            float4 p;
            p.x = __expf(-GAMMAK * fmaxf(fmaf(-2.0f, sa[0][j], qnv[0] + knc), 0.0f));
            p.y = __expf(-GAMMAK * fmaxf(fmaf(-2.0f, sa[1][j], qnv[1] + knc), 0.0f));
            p.z = __expf(-GAMMAK * fmaxf(fmaf(-2.0f, sa[2][j], qnv[2] + knc), 0.0f));
            p.w = __expf(-GAMMAK * fmaxf(fmaf(-2.0f, sa[3][j], qnv[3] + knc), 0.0f));
            PtW[(tc * 4 + j) * 17 + tr] = p;  // Pt[key][query], STS.128
        }
        __syncthreads();

        // ---- acc += P @ V ; den += rowsum(P) ----
        #pragma unroll 4
        for (int j = 0; j < 64; j++) {
            float4 p  = Pt4[j * 17 + tr];
            float4 v0 = Vs4[j * 32 + tc * 2];
            float4 v1 = Vs4[j * 32 + tc * 2 + 1];
            float pa[4] = {p.x, p.y, p.z, p.w};
            float vv[8] = {v0.x, v0.y, v0.z, v0.w, v1.x, v1.y, v1.z, v1.w};
            #pragma unroll
            for (int i = 0; i < 4; i++) {
                den[i] += pa[i];
                #pragma unroll
                for (int c = 0; c < 8; c++) acc[i][c] += pa[i] * vv[c];
            }
        }
        __syncthreads();   // before next tile overwrites Kt/Vs/kn_s
    }

    // ---- normalize + write ----
    float4* out4 = (float4*)out;
    #pragma unroll
    for (int i = 0; i < 4; i++) {
        int row = r0 + tr * 4 + i;
        if (row < NROWS) {
            float inv = 1.0f / den[i];
            float4 o0, o1;
            o0.x = acc[i][0] * inv;  o0.y = acc[i][1] * inv;
            o0.z = acc[i][2] * inv;  o0.w = acc[i][3] * inv;
            o1.x = acc[i][4] * inv;  o1.y = acc[i][5] * inv;
            o1.z = acc[i][6] * inv;  o1.w = acc[i][7] * inv;
            out4[row * 32 + tc * 2]     = o0;
            out4[row * 32 + tc * 2 + 1] = o1;
        }
    }
}

// ---------------- launch ----------------------------------------------------
extern "C" void kernel_launch(void* const* d_in, const int* in_sizes, int n_in,
                              void* d_out, int out_size)
{
    const float* X = (const float*)d_in[0];   // (8192,128)
    const float* y = (const float*)d_in[1];   // (8191,128)
    // d_in[2] = y_next : unused by reference output
    const float* R = (const float*)d_in[3];   // (128,128)
    const float* t = (const float*)d_in[4];   // (128,1)
    float* out = (float*)d_out;               // (8191,128)

    cudaFuncSetAttribute(yt_kernel,  cudaFuncAttributeMaxDynamicSharedMemorySize, 102400);
    cudaFuncSetAttribute(attn_kernel, cudaFuncAttributeMaxDynamicSharedMemorySize, 120320);

    yt_kernel<<<128, 256, 102400>>>(y, R, t);
    norm_kernel<<<dim3(8192, 2), 128>>>(X);
    attn_kernel<<<128, 256, 120320>>>(X, out);
}